// round 3
// baseline (speedup 1.0000x reference)
#include <cuda_runtime.h>
#include <cuda_bf16.h>
#include <math.h>

// ---------------- problem constants ----------------
#define BATCH 32
#define HH 64
#define WW 64
#define CH 192
#define LL (HH*WW)            // 4096
#define NHEAD 6
#define HD 32                 // head dim
#define WSZ 8
#define SHIFT 4
#define NTOK 64               // tokens per window
#define NWIN 64               // windows per image
#define MROWS (BATCH*LL)      // 131072 rows
#define CHID (4*CH)           // 768

// ---------------- scratch (device globals; no allocs allowed) ----------------
__device__ float g_xn  [MROWS*CH];    // LN1 output
__device__ float g_qkv [MROWS*3*CH];  // qkv, window-row order
__device__ float g_attn[MROWS*CH];    // attention output, window-row order
__device__ float g_x2  [MROWS*CH];    // x + attn (image-row order)
__device__ float g_xn2 [MROWS*CH];    // LN2 output
__device__ float g_h1  [MROWS*CHID];  // MLP hidden

// Map window-order row -> image-order row (fuses roll(-4,-4) + window partition;
// its inverse is identical, so the same map is used for the proj scatter).
__device__ __forceinline__ int win_to_img_row(int r) {
    int b   = r >> 12;            // 4096 window-rows per image
    int rem = r & 4095;
    int win = rem >> 6;
    int n   = rem & 63;
    int hs  = ((win >> 3) << 3) + (n >> 3);
    int ws  = ((win & 7)  << 3) + (n & 7);
    int hh  = (hs + SHIFT) & 63;
    int ww  = (ws + SHIFT) & 63;
    return (b << 12) + (hh << 6) + ww;
}

// ---------------- LayerNorm: one block per row, 192 threads ----------------
__global__ void ln_kernel(const float* __restrict__ x, const float* __restrict__ g,
                          const float* __restrict__ b, float* __restrict__ out) {
    int row = blockIdx.x;
    int t = threadIdx.x;
    float v = x[row*CH + t];
    float s = v, s2 = v*v;
    #pragma unroll
    for (int o = 16; o > 0; o >>= 1) {
        s  += __shfl_down_sync(0xffffffffu, s,  o);
        s2 += __shfl_down_sync(0xffffffffu, s2, o);
    }
    __shared__ float red[12];
    int wid = t >> 5, lane = t & 31;
    if (lane == 0) { red[wid] = s; red[6+wid] = s2; }
    __syncthreads();
    if (t == 0) {
        float a = 0.f, c = 0.f;
        #pragma unroll
        for (int i = 0; i < 6; i++) { a += red[i]; c += red[6+i]; }
        red[0] = a; red[6] = c;
    }
    __syncthreads();
    float mean = red[0] * (1.0f/CH);
    float var  = red[6] * (1.0f/CH) - mean*mean;
    float inv  = rsqrtf(var + 1e-5f);
    out[row*CH + t] = (v - mean) * inv * g[t] + b[t];
}

// ---------------- generic tiled fp32 GEMM: C[M,N] = A[M,K] @ Bw[N,K]^T ----------------
// MODE 0: A rows gathered via win_to_img_row (QKV), epilogue = +bias
// MODE 1: epilogue = scatter row via win_to_img_row, +bias +residual (proj)
// MODE 2: epilogue = gelu(acc+bias)                                  (fc1)
// MODE 3: epilogue = +bias +residual (direct rows)                   (fc2)
template<int MODE>
__global__ __launch_bounds__(256)
void gemm_kernel(const float* __restrict__ A, const float* __restrict__ Bw,
                 const float* __restrict__ bias, const float* __restrict__ resid,
                 float* __restrict__ Cout, int K, int Ncols) {
    const int BM = 128, BN = 64, BK = 16;
    __shared__ float As[BK][BM+1];
    __shared__ float Bs[BK][BN+1];
    __shared__ int rowIdx[BM];

    int tid = threadIdx.x;
    int rowBase = blockIdx.y * BM;
    int colBase = blockIdx.x * BN;

    if (tid < BM) {
        int r = rowBase + tid;
        rowIdx[tid] = (MODE == 0) ? win_to_img_row(r) : r;
    }
    __syncthreads();

    float acc[8][4];
    #pragma unroll
    for (int i = 0; i < 8; i++)
        #pragma unroll
        for (int j = 0; j < 4; j++) acc[i][j] = 0.f;

    int tm0 = (tid >> 4) << 3;   // 0..120 step 8
    int tn0 = (tid & 15) << 2;   // 0..60  step 4

    for (int k0 = 0; k0 < K; k0 += BK) {
        #pragma unroll
        for (int i = 0; i < 8; i++) {
            int flat = tid + i*256;
            int m = flat >> 4, k = flat & 15;
            As[k][m] = A[rowIdx[m]*K + k0 + k];
        }
        #pragma unroll
        for (int i = 0; i < 4; i++) {
            int flat = tid + i*256;
            int n = flat >> 4, k = flat & 15;
            Bs[k][n] = Bw[(colBase + n)*K + k0 + k];
        }
        __syncthreads();
        #pragma unroll
        for (int k = 0; k < BK; k++) {
            float a[8], bb[4];
            #pragma unroll
            for (int i = 0; i < 8; i++) a[i] = As[k][tm0 + i];
            #pragma unroll
            for (int j = 0; j < 4; j++) bb[j] = Bs[k][tn0 + j];
            #pragma unroll
            for (int i = 0; i < 8; i++)
                #pragma unroll
                for (int j = 0; j < 4; j++)
                    acc[i][j] = fmaf(a[i], bb[j], acc[i][j]);
        }
        __syncthreads();
    }

    #pragma unroll
    for (int i = 0; i < 8; i++) {
        int row = rowBase + tm0 + i;
        #pragma unroll
        for (int j = 0; j < 4; j++) {
            int col = colBase + tn0 + j;
            float v = acc[i][j] + bias[col];
            if (MODE == 1) {
                int dst = win_to_img_row(row);
                Cout[dst*Ncols + col] = resid[dst*Ncols + col] + v;
            } else if (MODE == 2) {
                Cout[row*Ncols + col] = 0.5f * v * (1.0f + erff(v * 0.70710678118654752f));
            } else if (MODE == 3) {
                Cout[row*Ncols + col] = resid[row*Ncols + col] + v;
            } else {
                Cout[row*Ncols + col] = v;
            }
        }
    }
}

// ---------------- attention: one block per (head, window), 64 threads ----------------
__device__ __forceinline__ int region_of(int p) {
    // slices (0,-8),(-8,-4),(-4,None) on a 64-grid
    return (p < 56) ? 0 : ((p < 60) ? 1 : 2);
}

__global__ __launch_bounds__(64)
void attn_kernel(const float* __restrict__ qkv, const float* __restrict__ rpb,
                 float* __restrict__ out) {
    int head = blockIdx.x;
    int g    = blockIdx.y;      // global window index [0, 2048)
    int n    = threadIdx.x;     // token row

    __shared__ float ks[NTOK][HD];
    __shared__ float vs[NTOK][HD];

    int rowbase = g * NTOK;
    // cooperative coalesced load of K and V tiles for this head
    for (int idx = n; idx < NTOK*HD; idx += NTOK) {
        int m = idx >> 5, d = idx & 31;
        const float* src = qkv + (rowbase + m)*(3*CH) + head*HD;
        ks[m][d] = src[CH   + d];
        vs[m][d] = src[2*CH + d];
    }
    float q[HD];
    {
        const float scale = 0.17677669529663687f; // 1/sqrt(32)
        const float* src = qkv + (rowbase + n)*(3*CH) + head*HD;
        #pragma unroll
        for (int d = 0; d < HD; d++) q[d] = src[d] * scale;
    }
    __syncthreads();

    int in_ = n >> 3, jn = n & 7;
    int win = g & 63;
    int wr = win >> 3, wc = win & 7;
    int reg_n = region_of(wr*8 + in_)*3 + region_of(wc*8 + jn);

    float s[NTOK];
    float mx = -1e30f;
    #pragma unroll 4
    for (int m = 0; m < NTOK; m++) {
        float dot = 0.f;
        #pragma unroll
        for (int d = 0; d < HD; d++) dot = fmaf(q[d], ks[m][d], dot);
        int im = m >> 3, jm = m & 7;
        int bidx = (in_ - im + 7)*15 + (jn - jm + 7);
        float bv = rpb[bidx*NHEAD + head];
        int reg_m = region_of(wr*8 + im)*3 + region_of(wc*8 + jm);
        float mv = (reg_n == reg_m) ? 0.f : -100.f;
        float val = dot + bv + mv;
        s[m] = val;
        mx = fmaxf(mx, val);
    }
    float sum = 0.f;
    #pragma unroll 4
    for (int m = 0; m < NTOK; m++) {
        float e = expf(s[m] - mx);
        s[m] = e;
        sum += e;
    }
    float rinv = 1.0f / sum;

    float accv[HD];
    #pragma unroll
    for (int d = 0; d < HD; d++) accv[d] = 0.f;
    #pragma unroll 4
    for (int m = 0; m < NTOK; m++) {
        float p = s[m];
        #pragma unroll
        for (int d = 0; d < HD; d++) accv[d] = fmaf(p, vs[m][d], accv[d]);
    }
    float* dst = out + (rowbase + n)*CH + head*HD;
    #pragma unroll
    for (int d = 0; d < HD; d++) dst[d] = accv[d] * rinv;
}

// ---------------- launch ----------------
extern "C" void kernel_launch(void* const* d_in, const int* in_sizes, int n_in,
                              void* d_out, int out_size) {
    const float* x       = (const float*)d_in[0];
    // d_in[1]=h, d_in[2]=w (constants 64, ignored)
    const float* norm1_g = (const float*)d_in[3];
    const float* norm1_b = (const float*)d_in[4];
    const float* qkv_w   = (const float*)d_in[5];
    const float* qkv_b   = (const float*)d_in[6];
    const float* rpb     = (const float*)d_in[7];
    const float* proj_w  = (const float*)d_in[8];
    const float* proj_b  = (const float*)d_in[9];
    const float* norm2_g = (const float*)d_in[10];
    const float* norm2_b = (const float*)d_in[11];
    const float* fc1_w   = (const float*)d_in[12];
    const float* fc1_b   = (const float*)d_in[13];
    const float* fc2_w   = (const float*)d_in[14];
    const float* fc2_b   = (const float*)d_in[15];
    float* out = (float*)d_out;

    float *xn, *qkv, *attn, *x2, *xn2, *h1;
    cudaGetSymbolAddress((void**)&xn,   g_xn);
    cudaGetSymbolAddress((void**)&qkv,  g_qkv);
    cudaGetSymbolAddress((void**)&attn, g_attn);
    cudaGetSymbolAddress((void**)&x2,   g_x2);
    cudaGetSymbolAddress((void**)&xn2,  g_xn2);
    cudaGetSymbolAddress((void**)&h1,   g_h1);

    // 1) LN1
    ln_kernel<<<MROWS, CH>>>(x, norm1_g, norm1_b, xn);
    // 2) QKV (gathered A: shift + window partition fused)
    gemm_kernel<0><<<dim3(3*CH/64, MROWS/128), 256>>>(xn, qkv_w, qkv_b, nullptr, qkv, CH, 3*CH);
    // 3) windowed attention (bias + shift mask computed in-kernel)
    attn_kernel<<<dim3(NHEAD, BATCH*NWIN), 64>>>(qkv, rpb, attn);
    // 4) proj + window reverse + roll + residual
    gemm_kernel<1><<<dim3(CH/64, MROWS/128), 256>>>(attn, proj_w, proj_b, x, x2, CH, CH);
    // 5) LN2
    ln_kernel<<<MROWS, CH>>>(x2, norm2_g, norm2_b, xn2);
    // 6) fc1 + GELU
    gemm_kernel<2><<<dim3(CHID/64, MROWS/128), 256>>>(xn2, fc1_w, fc1_b, nullptr, h1, CH, CHID);
    // 7) fc2 + residual -> out
    gemm_kernel<3><<<dim3(CH/64, MROWS/128), 256>>>(h1, fc2_w, fc2_b, x2, out, CHID, CH);
}

// round 4
// speedup vs baseline: 2.8292x; 2.8292x over previous
#include <cuda_runtime.h>
#include <cuda_bf16.h>
#include <math.h>

// ---------------- problem constants ----------------
#define BATCH 32
#define HH 64
#define WW 64
#define CH 192
#define LL (HH*WW)            // 4096
#define NHEAD 6
#define HD 32                 // head dim
#define WSZ 8
#define SHIFT 4
#define NTOK 64               // tokens per window
#define NWIN 64               // windows per image
#define MROWS (BATCH*LL)      // 131072 rows
#define CHID (4*CH)           // 768

// ---------------- scratch (device globals; no allocs allowed) ----------------
__device__ float g_xn  [MROWS*CH];    // LN1 output
__device__ float g_qkv [MROWS*3*CH];  // qkv, window-row order
__device__ float g_attn[MROWS*CH];    // attention output, window-row order
__device__ float g_x2  [MROWS*CH];    // x + attn (image-row order)
__device__ float g_xn2 [MROWS*CH];    // LN2 output
__device__ float g_h1  [MROWS*CHID];  // MLP hidden

// Map window-order row -> image-order row (fuses roll(-4,-4) + window partition;
// self-inverse, so the same map serves the proj scatter).
__device__ __forceinline__ int win_to_img_row(int r) {
    int b   = r >> 12;
    int rem = r & 4095;
    int win = rem >> 6;
    int n   = rem & 63;
    int hs  = ((win >> 3) << 3) + (n >> 3);
    int ws  = ((win & 7)  << 3) + (n & 7);
    int hh  = (hs + SHIFT) & 63;
    int ww  = (ws + SHIFT) & 63;
    return (b << 12) + (hh << 6) + ww;
}

// ---------------- tf32 helpers ----------------
__device__ __forceinline__ unsigned f2tf32(float f) {
    unsigned r;
    asm("cvt.rna.tf32.f32 %0, %1;" : "=r"(r) : "f"(f));
    return r;
}

__device__ __forceinline__ void mma_tf32(float* d, const unsigned* a, const unsigned* b) {
    asm volatile(
        "mma.sync.aligned.m16n8k8.row.col.f32.tf32.tf32.f32 "
        "{%0,%1,%2,%3}, {%4,%5,%6,%7}, {%8,%9}, {%0,%1,%2,%3};"
        : "+f"(d[0]), "+f"(d[1]), "+f"(d[2]), "+f"(d[3])
        : "r"(a[0]), "r"(a[1]), "r"(a[2]), "r"(a[3]), "r"(b[0]), "r"(b[1]));
}

// ---------------- LayerNorm: one block per row, 192 threads ----------------
__global__ void ln_kernel(const float* __restrict__ x, const float* __restrict__ g,
                          const float* __restrict__ b, float* __restrict__ out) {
    int row = blockIdx.x;
    int t = threadIdx.x;
    float v = x[row*CH + t];
    float s = v, s2 = v*v;
    #pragma unroll
    for (int o = 16; o > 0; o >>= 1) {
        s  += __shfl_down_sync(0xffffffffu, s,  o);
        s2 += __shfl_down_sync(0xffffffffu, s2, o);
    }
    __shared__ float red[12];
    int wid = t >> 5, lane = t & 31;
    if (lane == 0) { red[wid] = s; red[6+wid] = s2; }
    __syncthreads();
    if (t == 0) {
        float a = 0.f, c = 0.f;
        #pragma unroll
        for (int i = 0; i < 6; i++) { a += red[i]; c += red[6+i]; }
        red[0] = a; red[6] = c;
    }
    __syncthreads();
    float mean = red[0] * (1.0f/CH);
    float var  = red[6] * (1.0f/CH) - mean*mean;
    float inv  = rsqrtf(var + 1e-5f);
    out[row*CH + t] = (v - mean) * inv * g[t] + b[t];
}

// ---------------- TF32 tensor-core GEMM: C[M,N] = A[M,K] @ Bw[N,K]^T ----------------
// BM=128, BN=64, BK=16. 256 threads = 8 warps (4m x 2n), warp tile 32x32.
// MODE 0: A rows gathered via win_to_img_row (QKV), +bias
// MODE 1: scatter rows via win_to_img_row, +bias +residual (proj)
// MODE 2: gelu(acc+bias)                                   (fc1)
// MODE 3: +bias +residual                                  (fc2)
template<int MODE>
__global__ __launch_bounds__(256)
void gemm_tc(const float* __restrict__ A, const float* __restrict__ Bw,
             const float* __restrict__ bias, const float* __restrict__ resid,
             float* __restrict__ Cout, int K, int Ncols) {
    const int BM = 128, BN = 64, BK = 16, SK = BK + 4;  // stride 20 words
    __shared__ __align__(16) unsigned As[BM][SK];
    __shared__ __align__(16) unsigned Bs[BN][SK];
    __shared__ int rowIdx[BM];

    int tid = threadIdx.x;
    int rowBase = blockIdx.y * BM;
    int colBase = blockIdx.x * BN;

    if (tid < BM) {
        int r = rowBase + tid;
        rowIdx[tid] = (MODE == 0) ? win_to_img_row(r) : r;
    }

    int w    = tid >> 5, lane = tid & 31;
    int g    = lane >> 2, tg   = lane & 3;
    int wm   = w >> 1,    wn   = w & 1;
    int mW   = wm * 32,   nW   = wn * 32;

    float acc[2][4][4];
    #pragma unroll
    for (int mt = 0; mt < 2; mt++)
        #pragma unroll
        for (int nt = 0; nt < 4; nt++)
            #pragma unroll
            for (int i = 0; i < 4; i++) acc[mt][nt][i] = 0.f;

    int ldRow = tid >> 2;          // 0..63
    int ldK   = (tid & 3) * 4;     // 0,4,8,12

    for (int k0 = 0; k0 < K; k0 += BK) {
        __syncthreads();   // also guards rowIdx on first iteration
        #pragma unroll
        for (int i = 0; i < 2; i++) {
            int row = ldRow + i * 64;
            const float4 v = *(const float4*)&A[(size_t)rowIdx[row]*K + k0 + ldK];
            uint4 t;
            t.x = f2tf32(v.x); t.y = f2tf32(v.y);
            t.z = f2tf32(v.z); t.w = f2tf32(v.w);
            *(uint4*)&As[row][ldK] = t;
        }
        {
            const float4 v = *(const float4*)&Bw[(size_t)(colBase + ldRow)*K + k0 + ldK];
            uint4 t;
            t.x = f2tf32(v.x); t.y = f2tf32(v.y);
            t.z = f2tf32(v.z); t.w = f2tf32(v.w);
            *(uint4*)&Bs[ldRow][ldK] = t;
        }
        __syncthreads();

        #pragma unroll
        for (int kk = 0; kk < BK; kk += 8) {
            unsigned aF[2][4], bF[4][2];
            #pragma unroll
            for (int mt = 0; mt < 2; mt++) {
                int m = mW + 16*mt + g;
                aF[mt][0] = As[m    ][kk + tg];
                aF[mt][1] = As[m + 8][kk + tg];
                aF[mt][2] = As[m    ][kk + tg + 4];
                aF[mt][3] = As[m + 8][kk + tg + 4];
            }
            #pragma unroll
            for (int nt = 0; nt < 4; nt++) {
                int n = nW + 8*nt + g;
                bF[nt][0] = Bs[n][kk + tg];
                bF[nt][1] = Bs[n][kk + tg + 4];
            }
            #pragma unroll
            for (int mt = 0; mt < 2; mt++)
                #pragma unroll
                for (int nt = 0; nt < 4; nt++)
                    mma_tf32(acc[mt][nt], aF[mt], bF[nt]);
        }
    }

    // epilogue: c0,c1 at (row, col..col+1); c2,c3 at (row+8, ...)
    #pragma unroll
    for (int mt = 0; mt < 2; mt++) {
        #pragma unroll
        for (int half = 0; half < 2; half++) {
            int row = rowBase + mW + 16*mt + g + half*8;
            int dst = (MODE == 1) ? win_to_img_row(row) : row;
            #pragma unroll
            for (int nt = 0; nt < 4; nt++) {
                int col = colBase + nW + 8*nt + 2*tg;
                float v0 = acc[mt][nt][half*2 + 0] + bias[col];
                float v1 = acc[mt][nt][half*2 + 1] + bias[col + 1];
                float2 o;
                if (MODE == 1 || MODE == 3) {
                    float2 r = *(const float2*)&resid[(size_t)dst*Ncols + col];
                    o.x = r.x + v0;
                    o.y = r.y + v1;
                } else if (MODE == 2) {
                    o.x = 0.5f * v0 * (1.0f + erff(v0 * 0.70710678118654752f));
                    o.y = 0.5f * v1 * (1.0f + erff(v1 * 0.70710678118654752f));
                } else {
                    o.x = v0; o.y = v1;
                }
                *(float2*)&Cout[(size_t)dst*Ncols + col] = o;
            }
        }
    }
}

// ---------------- attention: one block per (head, window), 64 threads ----------------
__device__ __forceinline__ int region_of(int p) {
    return (p < 56) ? 0 : ((p < 60) ? 1 : 2);
}

__global__ __launch_bounds__(64)
void attn_kernel(const float* __restrict__ qkv, const float* __restrict__ rpb,
                 float* __restrict__ out) {
    int head = blockIdx.x;
    int g    = blockIdx.y;
    int n    = threadIdx.x;

    __shared__ float ks[NTOK][HD];
    __shared__ float vs[NTOK][HD];

    int rowbase = g * NTOK;
    for (int idx = n; idx < NTOK*HD; idx += NTOK) {
        int m = idx >> 5, d = idx & 31;
        const float* src = qkv + (rowbase + m)*(3*CH) + head*HD;
        ks[m][d] = src[CH   + d];
        vs[m][d] = src[2*CH + d];
    }
    float q[HD];
    {
        const float scale = 0.17677669529663687f;
        const float* src = qkv + (rowbase + n)*(3*CH) + head*HD;
        #pragma unroll
        for (int d = 0; d < HD; d++) q[d] = src[d] * scale;
    }
    __syncthreads();

    int in_ = n >> 3, jn = n & 7;
    int win = g & 63;
    int wr = win >> 3, wc = win & 7;
    int reg_n = region_of(wr*8 + in_)*3 + region_of(wc*8 + jn);

    float s[NTOK];
    float mx = -1e30f;
    #pragma unroll 4
    for (int m = 0; m < NTOK; m++) {
        float dot = 0.f;
        #pragma unroll
        for (int d = 0; d < HD; d++) dot = fmaf(q[d], ks[m][d], dot);
        int im = m >> 3, jm = m & 7;
        int bidx = (in_ - im + 7)*15 + (jn - jm + 7);
        float bv = rpb[bidx*NHEAD + head];
        int reg_m = region_of(wr*8 + im)*3 + region_of(wc*8 + jm);
        float mv = (reg_n == reg_m) ? 0.f : -100.f;
        float val = dot + bv + mv;
        s[m] = val;
        mx = fmaxf(mx, val);
    }
    float sum = 0.f;
    #pragma unroll 4
    for (int m = 0; m < NTOK; m++) {
        float e = expf(s[m] - mx);
        s[m] = e;
        sum += e;
    }
    float rinv = 1.0f / sum;

    float accv[HD];
    #pragma unroll
    for (int d = 0; d < HD; d++) accv[d] = 0.f;
    #pragma unroll 4
    for (int m = 0; m < NTOK; m++) {
        float p = s[m];
        #pragma unroll
        for (int d = 0; d < HD; d++) accv[d] = fmaf(p, vs[m][d], accv[d]);
    }
    float* dst = out + (rowbase + n)*CH + head*HD;
    #pragma unroll
    for (int d = 0; d < HD; d++) dst[d] = accv[d] * rinv;
}

// ---------------- launch ----------------
extern "C" void kernel_launch(void* const* d_in, const int* in_sizes, int n_in,
                              void* d_out, int out_size) {
    const float* x       = (const float*)d_in[0];
    const float* norm1_g = (const float*)d_in[3];
    const float* norm1_b = (const float*)d_in[4];
    const float* qkv_w   = (const float*)d_in[5];
    const float* qkv_b   = (const float*)d_in[6];
    const float* rpb     = (const float*)d_in[7];
    const float* proj_w  = (const float*)d_in[8];
    const float* proj_b  = (const float*)d_in[9];
    const float* norm2_g = (const float*)d_in[10];
    const float* norm2_b = (const float*)d_in[11];
    const float* fc1_w   = (const float*)d_in[12];
    const float* fc1_b   = (const float*)d_in[13];
    const float* fc2_w   = (const float*)d_in[14];
    const float* fc2_b   = (const float*)d_in[15];
    float* out = (float*)d_out;

    float *xn, *qkv, *attn, *x2, *xn2, *h1;
    cudaGetSymbolAddress((void**)&xn,   g_xn);
    cudaGetSymbolAddress((void**)&qkv,  g_qkv);
    cudaGetSymbolAddress((void**)&attn, g_attn);
    cudaGetSymbolAddress((void**)&x2,   g_x2);
    cudaGetSymbolAddress((void**)&xn2,  g_xn2);
    cudaGetSymbolAddress((void**)&h1,   g_h1);

    // 1) LN1
    ln_kernel<<<MROWS, CH>>>(x, norm1_g, norm1_b, xn);
    // 2) QKV (gathered A: shift + window partition fused)
    gemm_tc<0><<<dim3(3*CH/64, MROWS/128), 256>>>(xn, qkv_w, qkv_b, nullptr, qkv, CH, 3*CH);
    // 3) windowed attention (bias + shift mask computed in-kernel)
    attn_kernel<<<dim3(NHEAD, BATCH*NWIN), 64>>>(qkv, rpb, attn);
    // 4) proj + window reverse + roll + residual
    gemm_tc<1><<<dim3(CH/64, MROWS/128), 256>>>(attn, proj_w, proj_b, x, x2, CH, CH);
    // 5) LN2
    ln_kernel<<<MROWS, CH>>>(x2, norm2_g, norm2_b, xn2);
    // 6) fc1 + GELU
    gemm_tc<2><<<dim3(CHID/64, MROWS/128), 256>>>(xn2, fc1_w, fc1_b, nullptr, h1, CH, CHID);
    // 7) fc2 + residual -> out
    gemm_tc<3><<<dim3(CH/64, MROWS/128), 256>>>(h1, fc2_w, fc2_b, x2, out, CHID, CH);
}

// round 5
// speedup vs baseline: 4.3113x; 1.5238x over previous
#include <cuda_runtime.h>
#include <cuda_bf16.h>
#include <math.h>

// ---------------- problem constants ----------------
#define BATCH 32
#define HH 64
#define WW 64
#define CH 192
#define LL (HH*WW)            // 4096
#define NHEAD 6
#define HD 32                 // head dim
#define WSZ 8
#define SHIFT 4
#define NTOK 64               // tokens per window
#define NWIN 64               // windows per image
#define MROWS (BATCH*LL)      // 131072 rows
#define CHID (4*CH)           // 768

// ---------------- scratch (device globals; no allocs allowed) ----------------
__device__ float g_xn  [MROWS*CH];    // LN1 output
__device__ float g_qkv [MROWS*3*CH];  // qkv, window-row order
__device__ float g_attn[MROWS*CH];    // attention output, window-row order
__device__ float g_x2  [MROWS*CH];    // x + attn (image-row order)
__device__ float g_xn2 [MROWS*CH];    // LN2 output
__device__ float g_h1  [MROWS*CHID];  // MLP hidden

// Map window-order row -> image-order row (fuses roll(-4,-4) + window partition;
// self-inverse, so the same map serves the proj scatter).
__device__ __forceinline__ int win_to_img_row(int r) {
    int b   = r >> 12;
    int rem = r & 4095;
    int win = rem >> 6;
    int n   = rem & 63;
    int hs  = ((win >> 3) << 3) + (n >> 3);
    int ws  = ((win & 7)  << 3) + (n & 7);
    int hh  = (hs + SHIFT) & 63;
    int ww  = (ws + SHIFT) & 63;
    return (b << 12) + (hh << 6) + ww;
}

// ---------------- bf16 helpers ----------------
__device__ __forceinline__ unsigned pack_bf16(float lo, float hi) {
    __nv_bfloat162 h = __floats2bfloat162_rn(lo, hi);
    return *(unsigned*)&h;
}

__device__ __forceinline__ void mma_bf16(float* d, const unsigned* a, const unsigned* b) {
    asm volatile(
        "mma.sync.aligned.m16n8k16.row.col.f32.bf16.bf16.f32 "
        "{%0,%1,%2,%3}, {%4,%5,%6,%7}, {%8,%9}, {%0,%1,%2,%3};"
        : "+f"(d[0]), "+f"(d[1]), "+f"(d[2]), "+f"(d[3])
        : "r"(a[0]), "r"(a[1]), "r"(a[2]), "r"(a[3]), "r"(b[0]), "r"(b[1]));
}

// ---------------- LayerNorm: one block per row, 192 threads ----------------
__global__ void ln_kernel(const float* __restrict__ x, const float* __restrict__ g,
                          const float* __restrict__ b, float* __restrict__ out) {
    int row = blockIdx.x;
    int t = threadIdx.x;
    float v = x[row*CH + t];
    float s = v, s2 = v*v;
    #pragma unroll
    for (int o = 16; o > 0; o >>= 1) {
        s  += __shfl_down_sync(0xffffffffu, s,  o);
        s2 += __shfl_down_sync(0xffffffffu, s2, o);
    }
    __shared__ float red[12];
    int wid = t >> 5, lane = t & 31;
    if (lane == 0) { red[wid] = s; red[6+wid] = s2; }
    __syncthreads();
    if (t == 0) {
        float a = 0.f, c = 0.f;
        #pragma unroll
        for (int i = 0; i < 6; i++) { a += red[i]; c += red[6+i]; }
        red[0] = a; red[6] = c;
    }
    __syncthreads();
    float mean = red[0] * (1.0f/CH);
    float var  = red[6] * (1.0f/CH) - mean*mean;
    float inv  = rsqrtf(var + 1e-5f);
    out[row*CH + t] = (v - mean) * inv * g[t] + b[t];
}

// ---------------- bf16 tensor-core GEMM: C[M,N] = A[M,K] @ Bw[N,K]^T ----------------
// BM=128, BN=96, BK=32. 256 threads = 8 warps (4m x 2n), warp tile 32x48.
// Smem word layout: phys = row*16 + (col ^ 2*(row&7))  — conflict-free for
// both STS.64 stores and all mma fragment LDS patterns (verified by hand).
// MODE 0: A rows gathered via win_to_img_row (QKV), +bias
// MODE 1: scatter rows via win_to_img_row, +bias +residual (proj)
// MODE 2: gelu(acc+bias)                                   (fc1)
// MODE 3: +bias +residual                                  (fc2)
template<int MODE>
__global__ __launch_bounds__(256, 2)
void gemm_tc(const float* __restrict__ A, const float* __restrict__ Bw,
             const float* __restrict__ bias, const float* __restrict__ resid,
             float* __restrict__ Cout, int K, int Ncols) {
    const int BM = 128, BN = 96, BK = 32;
    __shared__ __align__(16) unsigned As[BM*16];   // 8 KB
    __shared__ __align__(16) unsigned Bs[BN*16];   // 6 KB
    __shared__ int rowIdx[BM];

    int tid = threadIdx.x;
    int rowBase = blockIdx.y * BM;
    int colBase = blockIdx.x * BN;

    if (tid < BM) {
        int r = rowBase + tid;
        rowIdx[tid] = (MODE == 0) ? win_to_img_row(r) : r;
    }
    __syncthreads();

    // loader mapping: dword (2 words = 4 floats) granularity
    int lr = tid >> 3;            // 0..31 base row
    int lj = tid & 7;             // dword column (floats 4*lj .. 4*lj+3)
    int physcol = (2*lj) ^ (2*(lr & 7));   // swizzled word col (row&7 invariant under +32)

    size_t aRow[4];
    size_t bRow[3];
    #pragma unroll
    for (int i = 0; i < 4; i++) aRow[i] = (size_t)rowIdx[lr + 32*i] * K;
    #pragma unroll
    for (int i = 0; i < 3; i++) bRow[i] = (size_t)(colBase + lr + 32*i) * K;

    int w    = tid >> 5, lane = tid & 31;
    int g    = lane >> 2, tg   = lane & 3;
    int wm   = w >> 1,    wn   = w & 1;
    int mW   = wm * 32,   nW   = wn * 48;
    int g2   = 2 * g;

    float acc[2][6][4];
    #pragma unroll
    for (int mt = 0; mt < 2; mt++)
        #pragma unroll
        for (int nt = 0; nt < 6; nt++)
            #pragma unroll
            for (int i = 0; i < 4; i++) acc[mt][nt][i] = 0.f;

    int numT = K / BK;
    float4 aP[4], bP[3];

    // preload tile 0
    #pragma unroll
    for (int i = 0; i < 4; i++) aP[i] = *(const float4*)&A[aRow[i] + 4*lj];
    #pragma unroll
    for (int i = 0; i < 3; i++) bP[i] = *(const float4*)&Bw[bRow[i] + 4*lj];

    for (int t = 0; t < numT; t++) {
        if (t > 0) __syncthreads();          // smem free after prev compute
        #pragma unroll
        for (int i = 0; i < 4; i++) {
            int row = lr + 32*i;
            uint2 wv = make_uint2(pack_bf16(aP[i].x, aP[i].y), pack_bf16(aP[i].z, aP[i].w));
            *(uint2*)&As[row*16 + physcol] = wv;
        }
        #pragma unroll
        for (int i = 0; i < 3; i++) {
            int row = lr + 32*i;
            uint2 wv = make_uint2(pack_bf16(bP[i].x, bP[i].y), pack_bf16(bP[i].z, bP[i].w));
            *(uint2*)&Bs[row*16 + physcol] = wv;
        }
        __syncthreads();

        if (t + 1 < numT) {                  // prefetch next tile under the mma
            int k0 = (t + 1) * BK;
            #pragma unroll
            for (int i = 0; i < 4; i++) aP[i] = *(const float4*)&A[aRow[i] + k0 + 4*lj];
            #pragma unroll
            for (int i = 0; i < 3; i++) bP[i] = *(const float4*)&Bw[bRow[i] + k0 + 4*lj];
        }

        #pragma unroll
        for (int kk = 0; kk < 2; kk++) {
            int cb = kk * 8;
            unsigned aF[2][4], bF[6][2];
            #pragma unroll
            for (int mt = 0; mt < 2; mt++) {
                int m0 = mW + 16*mt + g;
                aF[mt][0] = As[m0*16       + ((cb + tg)     ^ g2)];
                aF[mt][1] = As[(m0+8)*16   + ((cb + tg)     ^ g2)];
                aF[mt][2] = As[m0*16       + ((cb + tg + 4) ^ g2)];
                aF[mt][3] = As[(m0+8)*16   + ((cb + tg + 4) ^ g2)];
            }
            #pragma unroll
            for (int nt = 0; nt < 6; nt++) {
                int n0 = nW + 8*nt + g;
                bF[nt][0] = Bs[n0*16 + ((cb + tg)     ^ g2)];
                bF[nt][1] = Bs[n0*16 + ((cb + tg + 4) ^ g2)];
            }
            #pragma unroll
            for (int mt = 0; mt < 2; mt++)
                #pragma unroll
                for (int nt = 0; nt < 6; nt++)
                    mma_bf16(acc[mt][nt], aF[mt], bF[nt]);
        }
    }

    // epilogue: c0,c1 at (row, col..col+1); c2,c3 at (row+8, ...)
    #pragma unroll
    for (int mt = 0; mt < 2; mt++) {
        #pragma unroll
        for (int half = 0; half < 2; half++) {
            int row = rowBase + mW + 16*mt + g + half*8;
            int dst = (MODE == 1) ? win_to_img_row(row) : row;
            #pragma unroll
            for (int nt = 0; nt < 6; nt++) {
                int col = colBase + nW + 8*nt + 2*tg;
                float2 bb = *(const float2*)&bias[col];
                float v0 = acc[mt][nt][half*2 + 0] + bb.x;
                float v1 = acc[mt][nt][half*2 + 1] + bb.y;
                float2 o;
                if (MODE == 1 || MODE == 3) {
                    float2 r = *(const float2*)&resid[(size_t)dst*Ncols + col];
                    o.x = r.x + v0;
                    o.y = r.y + v1;
                } else if (MODE == 2) {
                    o.x = 0.5f * v0 * (1.0f + erff(v0 * 0.70710678118654752f));
                    o.y = 0.5f * v1 * (1.0f + erff(v1 * 0.70710678118654752f));
                } else {
                    o.x = v0; o.y = v1;
                }
                *(float2*)&Cout[(size_t)dst*Ncols + col] = o;
            }
        }
    }
}

// ---------------- attention: one block per (head, window), 64 threads ----------------
__device__ __forceinline__ int region_of(int p) {
    return (p < 56) ? 0 : ((p < 60) ? 1 : 2);
}

__global__ __launch_bounds__(64)
void attn_kernel(const float* __restrict__ qkv, const float* __restrict__ rpb,
                 float* __restrict__ out) {
    int head = blockIdx.x;
    int g    = blockIdx.y;
    int n    = threadIdx.x;

    __shared__ float ks[NTOK][HD];
    __shared__ float vs[NTOK][HD];

    int rowbase = g * NTOK;
    for (int idx = n; idx < NTOK*HD; idx += NTOK) {
        int m = idx >> 5, d = idx & 31;
        const float* src = qkv + (rowbase + m)*(3*CH) + head*HD;
        ks[m][d] = src[CH   + d];
        vs[m][d] = src[2*CH + d];
    }
    float q[HD];
    {
        const float scale = 0.17677669529663687f;
        const float* src = qkv + (rowbase + n)*(3*CH) + head*HD;
        #pragma unroll
        for (int d = 0; d < HD; d++) q[d] = src[d] * scale;
    }
    __syncthreads();

    int in_ = n >> 3, jn = n & 7;
    int win = g & 63;
    int wr = win >> 3, wc = win & 7;
    int reg_n = region_of(wr*8 + in_)*3 + region_of(wc*8 + jn);

    float s[NTOK];
    float mx = -1e30f;
    #pragma unroll 4
    for (int m = 0; m < NTOK; m++) {
        float dot = 0.f;
        #pragma unroll
        for (int d = 0; d < HD; d++) dot = fmaf(q[d], ks[m][d], dot);
        int im = m >> 3, jm = m & 7;
        int bidx = (in_ - im + 7)*15 + (jn - jm + 7);
        float bv = rpb[bidx*NHEAD + head];
        int reg_m = region_of(wr*8 + im)*3 + region_of(wc*8 + jm);
        float mv = (reg_n == reg_m) ? 0.f : -100.f;
        float val = dot + bv + mv;
        s[m] = val;
        mx = fmaxf(mx, val);
    }
    float sum = 0.f;
    #pragma unroll 4
    for (int m = 0; m < NTOK; m++) {
        float e = expf(s[m] - mx);
        s[m] = e;
        sum += e;
    }
    float rinv = 1.0f / sum;

    float accv[HD];
    #pragma unroll
    for (int d = 0; d < HD; d++) accv[d] = 0.f;
    #pragma unroll 4
    for (int m = 0; m < NTOK; m++) {
        float p = s[m];
        #pragma unroll
        for (int d = 0; d < HD; d++) accv[d] = fmaf(p, vs[m][d], accv[d]);
    }
    float* dst = out + (rowbase + n)*CH + head*HD;
    #pragma unroll
    for (int d = 0; d < HD; d++) dst[d] = accv[d] * rinv;
}

// ---------------- launch ----------------
extern "C" void kernel_launch(void* const* d_in, const int* in_sizes, int n_in,
                              void* d_out, int out_size) {
    const float* x       = (const float*)d_in[0];
    const float* norm1_g = (const float*)d_in[3];
    const float* norm1_b = (const float*)d_in[4];
    const float* qkv_w   = (const float*)d_in[5];
    const float* qkv_b   = (const float*)d_in[6];
    const float* rpb     = (const float*)d_in[7];
    const float* proj_w  = (const float*)d_in[8];
    const float* proj_b  = (const float*)d_in[9];
    const float* norm2_g = (const float*)d_in[10];
    const float* norm2_b = (const float*)d_in[11];
    const float* fc1_w   = (const float*)d_in[12];
    const float* fc1_b   = (const float*)d_in[13];
    const float* fc2_w   = (const float*)d_in[14];
    const float* fc2_b   = (const float*)d_in[15];
    float* out = (float*)d_out;

    float *xn, *qkv, *attn, *x2, *xn2, *h1;
    cudaGetSymbolAddress((void**)&xn,   g_xn);
    cudaGetSymbolAddress((void**)&qkv,  g_qkv);
    cudaGetSymbolAddress((void**)&attn, g_attn);
    cudaGetSymbolAddress((void**)&x2,   g_x2);
    cudaGetSymbolAddress((void**)&xn2,  g_xn2);
    cudaGetSymbolAddress((void**)&h1,   g_h1);

    // 1) LN1
    ln_kernel<<<MROWS, CH>>>(x, norm1_g, norm1_b, xn);
    // 2) QKV (gathered A: shift + window partition fused)
    gemm_tc<0><<<dim3(3*CH/96, MROWS/128), 256>>>(xn, qkv_w, qkv_b, nullptr, qkv, CH, 3*CH);
    // 3) windowed attention (bias + shift mask computed in-kernel)
    attn_kernel<<<dim3(NHEAD, BATCH*NWIN), 64>>>(qkv, rpb, attn);
    // 4) proj + window reverse + roll + residual
    gemm_tc<1><<<dim3(CH/96, MROWS/128), 256>>>(attn, proj_w, proj_b, x, x2, CH, CH);
    // 5) LN2
    ln_kernel<<<MROWS, CH>>>(x2, norm2_g, norm2_b, xn2);
    // 6) fc1 + GELU
    gemm_tc<2><<<dim3(CHID/96, MROWS/128), 256>>>(xn2, fc1_w, fc1_b, nullptr, h1, CH, CHID);
    // 7) fc2 + residual -> out
    gemm_tc<3><<<dim3(CH/96, MROWS/128), 256>>>(h1, fc2_w, fc2_b, x2, out, CHID, CH);
}

// round 7
// speedup vs baseline: 4.7562x; 1.1032x over previous
#include <cuda_runtime.h>
#include <cuda_bf16.h>
#include <math.h>

// ---------------- problem constants ----------------
#define BATCH 32
#define HH 64
#define WW 64
#define CH 192
#define LL (HH*WW)            // 4096
#define NHEAD 6
#define HD 32                 // head dim
#define WSZ 8
#define SHIFT 4
#define NTOK 64               // tokens per window
#define NWIN 64               // windows per image
#define MROWS (BATCH*LL)      // 131072 rows
#define CHID (4*CH)           // 768

// ---------------- scratch (device globals; no allocs allowed) ----------------
// All intermediates bf16 (GEMM rounds A to bf16 anyway); residual spine fp32.
__device__ __nv_bfloat16 g_xn  [MROWS*CH];    // LN1 output
__device__ __nv_bfloat16 g_qkv [MROWS*3*CH];  // qkv, window-row order
__device__ __nv_bfloat16 g_attn[MROWS*CH];    // attention output, window-row order
__device__ float         g_x2  [MROWS*CH];    // x + attn (image-row order)
__device__ __nv_bfloat16 g_xn2 [MROWS*CH];    // LN2 output
__device__ __nv_bfloat16 g_h1  [MROWS*CHID];  // MLP hidden

// Map window-order row -> image-order row (fuses roll(-4,-4) + window partition;
// self-inverse, so the same map serves the proj scatter).
__device__ __forceinline__ int win_to_img_row(int r) {
    int b   = r >> 12;
    int rem = r & 4095;
    int win = rem >> 6;
    int n   = rem & 63;
    int hs  = ((win >> 3) << 3) + (n >> 3);
    int ws  = ((win & 7)  << 3) + (n & 7);
    int hh  = (hs + SHIFT) & 63;
    int ww  = (ws + SHIFT) & 63;
    return (b << 12) + (hh << 6) + ww;
}

// ---------------- bf16 helpers ----------------
__device__ __forceinline__ unsigned pack_bf16(float lo, float hi) {
    __nv_bfloat162 h = __floats2bfloat162_rn(lo, hi);
    return *(unsigned*)&h;
}

__device__ __forceinline__ void mma_bf16(float* d, const unsigned* a, const unsigned* b) {
    asm volatile(
        "mma.sync.aligned.m16n8k16.row.col.f32.bf16.bf16.f32 "
        "{%0,%1,%2,%3}, {%4,%5,%6,%7}, {%8,%9}, {%0,%1,%2,%3};"
        : "+f"(d[0]), "+f"(d[1]), "+f"(d[2]), "+f"(d[3])
        : "r"(a[0]), "r"(a[1]), "r"(a[2]), "r"(a[3]), "r"(b[0]), "r"(b[1]));
}

// ---------------- LayerNorm: one block per row, 192 threads, bf16 out ----------------
__global__ void ln_kernel(const float* __restrict__ x, const float* __restrict__ g,
                          const float* __restrict__ b, __nv_bfloat16* __restrict__ out) {
    int row = blockIdx.x;
    int t = threadIdx.x;
    float v = x[row*CH + t];
    float s = v, s2 = v*v;
    #pragma unroll
    for (int o = 16; o > 0; o >>= 1) {
        s  += __shfl_down_sync(0xffffffffu, s,  o);
        s2 += __shfl_down_sync(0xffffffffu, s2, o);
    }
    __shared__ float red[12];
    int wid = t >> 5, lane = t & 31;
    if (lane == 0) { red[wid] = s; red[6+wid] = s2; }
    __syncthreads();
    if (t == 0) {
        float a = 0.f, c = 0.f;
        #pragma unroll
        for (int i = 0; i < 6; i++) { a += red[i]; c += red[6+i]; }
        red[0] = a; red[6] = c;
    }
    __syncthreads();
    float mean = red[0] * (1.0f/CH);
    float var  = red[6] * (1.0f/CH) - mean*mean;
    float inv  = rsqrtf(var + 1e-5f);
    out[row*CH + t] = __float2bfloat16((v - mean) * inv * g[t] + b[t]);
}

// ---------------- bf16 tensor-core GEMM: C[M,N] = A[M,K] @ Bw[N,K]^T ----------------
// A is bf16 in gmem (all modes). Bw is fp32 weights (converted in loader).
// BM=128, BN=96, BK=32. 256 threads = 8 warps (4m x 2n), warp tile 32x48.
// Smem word layout: phys = row*16 + (col ^ 2*(row&7)) — conflict-free for
// uint2 stores and all mma fragment LDS patterns.
// MODE 0: A rows gathered via win_to_img_row (QKV), +bias, bf16 out
// MODE 1: scatter rows via win_to_img_row, +bias +residual, fp32 out (proj)
// MODE 2: gelu(acc+bias), bf16 out                                  (fc1)
// MODE 3: +bias +residual, fp32 out                                 (fc2)
template<int MODE>
__global__ __launch_bounds__(256, 2)
void gemm_tc(const __nv_bfloat16* __restrict__ A, const float* __restrict__ Bw,
             const float* __restrict__ bias, const float* __restrict__ resid,
             void* __restrict__ CoutV, int K, int Ncols) {
    const int BM = 128, BN = 96, BK = 32;
    __shared__ __align__(16) unsigned As[BM*16];   // 8 KB
    __shared__ __align__(16) unsigned Bs[BN*16];   // 6 KB
    __shared__ int rowIdx[BM];

    int tid = threadIdx.x;
    int rowBase = blockIdx.y * BM;
    int colBase = blockIdx.x * BN;

    if (tid < BM) {
        int r = rowBase + tid;
        rowIdx[tid] = (MODE == 0) ? win_to_img_row(r) : r;
    }
    __syncthreads();

    // loader mapping: uint2 (4 bf16) granularity
    int lr = tid >> 3;            // 0..31 base row
    int lj = tid & 7;             // chunk col (bf16 elems 4*lj .. 4*lj+3)
    int physcol = (2*lj) ^ (2*(lr & 7));   // swizzled word col

    size_t aRow[4];
    size_t bRow[3];
    #pragma unroll
    for (int i = 0; i < 4; i++) aRow[i] = (size_t)rowIdx[lr + 32*i] * K;
    #pragma unroll
    for (int i = 0; i < 3; i++) bRow[i] = (size_t)(colBase + lr + 32*i) * K;

    int w    = tid >> 5, lane = tid & 31;
    int g    = lane >> 2, tg   = lane & 3;
    int wm   = w >> 1,    wn   = w & 1;
    int mW   = wm * 32,   nW   = wn * 48;
    int g2   = 2 * g;

    float acc[2][6][4];
    #pragma unroll
    for (int mt = 0; mt < 2; mt++)
        #pragma unroll
        for (int nt = 0; nt < 6; nt++)
            #pragma unroll
            for (int i = 0; i < 4; i++) acc[mt][nt][i] = 0.f;

    int numT = K / BK;
    uint2  aP[4];
    float4 bP[3];

    // preload tile 0
    #pragma unroll
    for (int i = 0; i < 4; i++) aP[i] = *(const uint2*)&A[aRow[i] + 4*lj];
    #pragma unroll
    for (int i = 0; i < 3; i++) bP[i] = *(const float4*)&Bw[bRow[i] + 4*lj];

    for (int t = 0; t < numT; t++) {
        if (t > 0) __syncthreads();          // smem free after prev compute
        #pragma unroll
        for (int i = 0; i < 4; i++) {
            int row = lr + 32*i;
            *(uint2*)&As[row*16 + physcol] = aP[i];
        }
        #pragma unroll
        for (int i = 0; i < 3; i++) {
            int row = lr + 32*i;
            uint2 wv = make_uint2(pack_bf16(bP[i].x, bP[i].y), pack_bf16(bP[i].z, bP[i].w));
            *(uint2*)&Bs[row*16 + physcol] = wv;
        }
        __syncthreads();

        if (t + 1 < numT) {                  // prefetch next tile under the mma
            int k0 = (t + 1) * BK;
            #pragma unroll
            for (int i = 0; i < 4; i++) aP[i] = *(const uint2*)&A[aRow[i] + k0 + 4*lj];
            #pragma unroll
            for (int i = 0; i < 3; i++) bP[i] = *(const float4*)&Bw[bRow[i] + k0 + 4*lj];
        }

        #pragma unroll
        for (int kk = 0; kk < 2; kk++) {
            int cb = kk * 8;
            unsigned aF[2][4], bF[6][2];
            #pragma unroll
            for (int mt = 0; mt < 2; mt++) {
                int m0 = mW + 16*mt + g;
                aF[mt][0] = As[m0*16       + ((cb + tg)     ^ g2)];
                aF[mt][1] = As[(m0+8)*16   + ((cb + tg)     ^ g2)];
                aF[mt][2] = As[m0*16       + ((cb + tg + 4) ^ g2)];
                aF[mt][3] = As[(m0+8)*16   + ((cb + tg + 4) ^ g2)];
            }
            #pragma unroll
            for (int nt = 0; nt < 6; nt++) {
                int n0 = nW + 8*nt + g;
                bF[nt][0] = Bs[n0*16 + ((cb + tg)     ^ g2)];
                bF[nt][1] = Bs[n0*16 + ((cb + tg + 4) ^ g2)];
            }
            #pragma unroll
            for (int mt = 0; mt < 2; mt++)
                #pragma unroll
                for (int nt = 0; nt < 6; nt++)
                    mma_bf16(acc[mt][nt], aF[mt], bF[nt]);
        }
    }

    // epilogue: c0,c1 at (row, col..col+1); c2,c3 at (row+8, ...)
    float*         CoutF = (float*)CoutV;
    __nv_bfloat16* CoutB = (__nv_bfloat16*)CoutV;
    #pragma unroll
    for (int mt = 0; mt < 2; mt++) {
        #pragma unroll
        for (int half = 0; half < 2; half++) {
            int row = rowBase + mW + 16*mt + g + half*8;
            int dst = (MODE == 1) ? win_to_img_row(row) : row;
            #pragma unroll
            for (int nt = 0; nt < 6; nt++) {
                int col = colBase + nW + 8*nt + 2*tg;
                float2 bb = *(const float2*)&bias[col];
                float v0 = acc[mt][nt][half*2 + 0] + bb.x;
                float v1 = acc[mt][nt][half*2 + 1] + bb.y;
                if (MODE == 1 || MODE == 3) {
                    float2 r = *(const float2*)&resid[(size_t)dst*Ncols + col];
                    float2 o; o.x = r.x + v0; o.y = r.y + v1;
                    *(float2*)&CoutF[(size_t)dst*Ncols + col] = o;
                } else if (MODE == 2) {
                    float o0 = 0.5f * v0 * (1.0f + erff(v0 * 0.70710678118654752f));
                    float o1 = 0.5f * v1 * (1.0f + erff(v1 * 0.70710678118654752f));
                    *(__nv_bfloat162*)&CoutB[(size_t)dst*Ncols + col] = __floats2bfloat162_rn(o0, o1);
                } else {
                    *(__nv_bfloat162*)&CoutB[(size_t)dst*Ncols + col] = __floats2bfloat162_rn(v0, v1);
                }
            }
        }
    }
}

// ---------------- attention: one block per (head, window), 64 threads ----------------
__device__ __forceinline__ int region_of(int p) {
    return (p < 56) ? 0 : ((p < 60) ? 1 : 2);
}

__global__ __launch_bounds__(64)
void attn_kernel(const __nv_bfloat16* __restrict__ qkv, const float* __restrict__ rpb,
                 __nv_bfloat16* __restrict__ out) {
    int head = blockIdx.x;
    int g    = blockIdx.y;
    int n    = threadIdx.x;

    __shared__ float ks[NTOK][HD];
    __shared__ float vs[NTOK][HD];

    int rowbase = g * NTOK;
    for (int idx = n; idx < NTOK*HD; idx += NTOK) {
        int m = idx >> 5, d = idx & 31;
        const __nv_bfloat16* src = qkv + (size_t)(rowbase + m)*(3*CH) + head*HD;
        ks[m][d] = __bfloat162float(src[CH   + d]);
        vs[m][d] = __bfloat162float(src[2*CH + d]);
    }
    float q[HD];
    {
        const float scale = 0.17677669529663687f;
        const __nv_bfloat16* src = qkv + (size_t)(rowbase + n)*(3*CH) + head*HD;
        #pragma unroll
        for (int d = 0; d < HD; d += 2) {
            __nv_bfloat162 p = *(const __nv_bfloat162*)&src[d];
            q[d]   = __bfloat162float(p.x) * scale;
            q[d+1] = __bfloat162float(p.y) * scale;
        }
    }
    __syncthreads();

    int in_ = n >> 3, jn = n & 7;
    int win = g & 63;
    int wr = win >> 3, wc = win & 7;
    int reg_n = region_of(wr*8 + in_)*3 + region_of(wc*8 + jn);

    float s[NTOK];
    float mx = -1e30f;
    #pragma unroll 4
    for (int m = 0; m < NTOK; m++) {
        float dot = 0.f;
        #pragma unroll
        for (int d = 0; d < HD; d++) dot = fmaf(q[d], ks[m][d], dot);
        int im = m >> 3, jm = m & 7;
        int bidx = (in_ - im + 7)*15 + (jn - jm + 7);
        float bv = rpb[bidx*NHEAD + head];
        int reg_m = region_of(wr*8 + im)*3 + region_of(wc*8 + jm);
        float mv = (reg_n == reg_m) ? 0.f : -100.f;
        float val = dot + bv + mv;
        s[m] = val;
        mx = fmaxf(mx, val);
    }
    float sum = 0.f;
    #pragma unroll 4
    for (int m = 0; m < NTOK; m++) {
        float e = expf(s[m] - mx);
        s[m] = e;
        sum += e;
    }
    float rinv = 1.0f / sum;

    float accv[HD];
    #pragma unroll
    for (int d = 0; d < HD; d++) accv[d] = 0.f;
    #pragma unroll 4
    for (int m = 0; m < NTOK; m++) {
        float p = s[m];
        #pragma unroll
        for (int d = 0; d < HD; d++) accv[d] = fmaf(p, vs[m][d], accv[d]);
    }
    __nv_bfloat16* dst = out + (size_t)(rowbase + n)*CH + head*HD;
    #pragma unroll
    for (int d = 0; d < HD; d += 2)
        *(__nv_bfloat162*)&dst[d] = __floats2bfloat162_rn(accv[d]*rinv, accv[d+1]*rinv);
}

// ---------------- launch ----------------
extern "C" void kernel_launch(void* const* d_in, const int* in_sizes, int n_in,
                              void* d_out, int out_size) {
    const float* x       = (const float*)d_in[0];
    const float* norm1_g = (const float*)d_in[3];
    const float* norm1_b = (const float*)d_in[4];
    const float* qkv_w   = (const float*)d_in[5];
    const float* qkv_b   = (const float*)d_in[6];
    const float* rpb     = (const float*)d_in[7];
    const float* proj_w  = (const float*)d_in[8];
    const float* proj_b  = (const float*)d_in[9];
    const float* norm2_g = (const float*)d_in[10];
    const float* norm2_b = (const float*)d_in[11];
    const float* fc1_w   = (const float*)d_in[12];
    const float* fc1_b   = (const float*)d_in[13];
    const float* fc2_w   = (const float*)d_in[14];
    const float* fc2_b   = (const float*)d_in[15];
    float* out = (float*)d_out;

    __nv_bfloat16 *xn, *qkv, *attn, *xn2, *h1;
    float *x2;
    cudaGetSymbolAddress((void**)&xn,   g_xn);
    cudaGetSymbolAddress((void**)&qkv,  g_qkv);
    cudaGetSymbolAddress((void**)&attn, g_attn);
    cudaGetSymbolAddress((void**)&x2,   g_x2);
    cudaGetSymbolAddress((void**)&xn2,  g_xn2);
    cudaGetSymbolAddress((void**)&h1,   g_h1);

    // 1) LN1
    ln_kernel<<<MROWS, CH>>>(x, norm1_g, norm1_b, xn);
    // 2) QKV (gathered A: shift + window partition fused)
    gemm_tc<0><<<dim3(3*CH/96, MROWS/128), 256>>>(xn, qkv_w, qkv_b, nullptr, qkv, CH, 3*CH);
    // 3) windowed attention (bias + shift mask computed in-kernel)
    attn_kernel<<<dim3(NHEAD, BATCH*NWIN), 64>>>(qkv, rpb, attn);
    // 4) proj + window reverse + roll + residual
    gemm_tc<1><<<dim3(CH/96, MROWS/128), 256>>>(attn, proj_w, proj_b, x, x2, CH, CH);
    // 5) LN2
    ln_kernel<<<MROWS, CH>>>(x2, norm2_g, norm2_b, xn2);
    // 6) fc1 + GELU
    gemm_tc<2><<<dim3(CHID/96, MROWS/128), 256>>>(xn2, fc1_w, fc1_b, nullptr, h1, CH, CHID);
    // 7) fc2 + residual -> out
    gemm_tc<3><<<dim3(CH/96, MROWS/128), 256>>>(h1, fc2_w, fc2_b, x2, out, CHID, CH);
}